// round 12
// baseline (speedup 1.0000x reference)
#include <cuda_runtime.h>
#include <cstdint>
#include <cstddef>

// ---------------- problem constants ----------------
#define BS    8
#define NFEAT 64
#define NND   2048
#define JDIM  3
#define CH    128                  // 2*NOUT
#define KDIM  6144                 // NND*JDIM
#define ZN    (BS*CH*NND)          // 2097152 zbn elements
#define CHUNK 64                   // fp32 of K per chunk (256 B per row)
#define NCH   (KDIM/CHUNK)         // 96
#define STAGES 3
#define MT    128                  // m-rows per CTA tile
#define WTILEB (MT*CHUNK*4)        // 32768 W tile bytes
#define PTILEB (128*CHUNK*4)       // 32768 P tile bytes
#define STAGEB (WTILEB+PTILEB)     // 65536
#define DYN2  (STAGES*STAGEB)      // 196608
#define THR2  192                  // 4 MMA warps + 2 producer warps
#define NSLOT (128*4)              // stats partial slots
#define DYN1  147456               // k1: As 32KB + Xs 16KB + stage 96KB

// ---------------- device scratch ----------------
__device__ float g_P[(size_t)BS*CH*KDIM];   // 25.2 MB
__device__ float g_z[(size_t)ZN];           // 8.4 MB
__device__ float g_pS1[NSLOT*CH];
__device__ float g_pS2[NSLOT*CH];
__device__ float g_misc[2];                 // total, M0
__device__ float g_scale[CH];
__device__ float g_shift[CH];

// ---------------- helpers ----------------
__device__ __forceinline__ uint32_t smem_u32(const void* p) {
    uint32_t a;
    asm("{ .reg .u64 t; cvta.to.shared.u64 t, %1; cvt.u32.u64 %0, t; }" : "=r"(a) : "l"(p));
    return a;
}
__device__ __forceinline__ void cp_async16(uint32_t dst, const void* src) {
    asm volatile("cp.async.cg.shared.global [%0], [%1], 16;" :: "r"(dst), "l"(src) : "memory");
}
#define CP_COMMIT() asm volatile("cp.async.commit_group;" ::: "memory")
#define CP_WAIT(n)  asm volatile("cp.async.wait_group %0;" :: "n"(n) : "memory")
#define MEMBAR_CTA() asm volatile("membar.cta;" ::: "memory")
#define BAR_SYNC(id)   asm volatile("bar.sync %0, %1;"   :: "r"(id), "n"(THR2) : "memory")
#define BAR_ARRIVE(id) asm volatile("bar.arrive %0, %1;" :: "r"(id), "n"(THR2) : "memory")

__device__ __forceinline__ void mma_tf32(float* d, const uint32_t* a, const uint32_t* b) {
    asm volatile(
        "mma.sync.aligned.m16n8k8.row.col.f32.tf32.tf32.f32 "
        "{%0,%1,%2,%3}, {%4,%5,%6,%7}, {%8,%9}, {%0,%1,%2,%3};"
        : "+f"(d[0]), "+f"(d[1]), "+f"(d[2]), "+f"(d[3])
        : "r"(a[0]), "r"(a[1]), "r"(a[2]), "r"(a[3]), "r"(b[0]), "r"(b[1]));
}
__device__ __forceinline__ void ldmx4(uint32_t* r, uint32_t addr) {
    asm volatile(
        "ldmatrix.sync.aligned.m8n8.x4.shared.b16 {%0,%1,%2,%3}, [%4];"
        : "=r"(r[0]), "=r"(r[1]), "=r"(r[2]), "=r"(r[3]) : "r"(addr));
}
// 256B-row tile: seg = 16B unit 0..15; swizzle each 128B half independently
__device__ __forceinline__ int swz256(int row, int seg) {
    return row*256 + ((seg & 8) << 4) + ((((seg & 7) ^ (row & 7))) << 4);
}

// ---------------- K0: init reductions ----------------
__global__ void k0_init(const float* __restrict__ Nb, const float* __restrict__ mask) {
    int tid = threadIdx.x;
    float acc = 0.0f;
    for (int i = tid; i < BS*NND; i += 256) acc += mask[i];
    __shared__ float red[256];
    red[tid] = acc;
    __syncthreads();
    for (int s = 128; s > 0; s >>= 1) {
        if (tid < s) red[tid] += red[tid + s];
        __syncthreads();
    }
    if (tid == 0) {
        float tot = 0.0f;
        for (int i = 0; i < BS; i++) tot += Nb[i];
        g_misc[0] = tot;
        g_misc[1] = red[0];
    }
}

// ---------------- dummy kernel: keeps k2 in the ncu capture slot ----------------
__global__ void k_nop() {}

// ---------------- K1: P[b,o,n*3+j] = sum_f C[o, j*64+f] * X[b,f,n] ----------------
__global__ void __launch_bounds__(256, 1)
k1_gemm(const float* __restrict__ X, const float* __restrict__ cv1_w,
        const float* __restrict__ cv2_w) {
    extern __shared__ float sm1[];
    float* As    = sm1;            // [64 f][128 o]
    float* Xs    = sm1 + 8192;     // [64 f][64 n]
    float* stage = sm1 + 12288;    // [128 o][192 k']
    int tid = threadIdx.x;
    int nt = blockIdx.x, b = blockIdx.y;

    #pragma unroll
    for (int i = 0; i < 4; i++) {
        int q = i*256 + tid;
        int n4 = q & 15;
        int f  = q >> 4;
        float4 v = __ldg((const float4*)(X + ((size_t)(b*NFEAT + f))*NND + nt*64 + n4*4));
        *(float4*)(Xs + f*64 + n4*4) = v;
    }

    int tx = tid & 15, ty = tid >> 4;

    for (int j = 0; j < JDIM; j++) {
        __syncthreads();
        #pragma unroll
        for (int i = 0; i < 8; i++) {
            int q = i*256 + tid;
            int o  = q & 127;
            int f4 = q >> 7;
            const float* src = ((o < 64) ? (cv2_w + o*192) : (cv1_w + (o-64)*192)) + j*64 + f4*4;
            float4 v = __ldg((const float4*)src);
            As[(f4*4+0)*128 + o] = v.x;
            As[(f4*4+1)*128 + o] = v.y;
            As[(f4*4+2)*128 + o] = v.z;
            As[(f4*4+3)*128 + o] = v.w;
        }
        __syncthreads();

        float acc[8][4];
        #pragma unroll
        for (int i = 0; i < 8; i++)
            #pragma unroll
            for (int u = 0; u < 4; u++) acc[i][u] = 0.0f;

        #pragma unroll 8
        for (int f = 0; f < 64; f++) {
            float a[8], bb[4];
            *(float4*)(a)   = *(const float4*)(As + f*128 + ty*8);
            *(float4*)(a+4) = *(const float4*)(As + f*128 + ty*8 + 4);
            *(float4*)(bb)  = *(const float4*)(Xs + f*64 + tx*4);
            #pragma unroll
            for (int i = 0; i < 8; i++)
                #pragma unroll
                for (int u = 0; u < 4; u++)
                    acc[i][u] = fmaf(a[i], bb[u], acc[i][u]);
        }
        #pragma unroll
        for (int i = 0; i < 8; i++) {
            int o = ty*8 + i;
            #pragma unroll
            for (int u = 0; u < 4; u++)
                stage[o*192 + (tx*4 + u)*3 + j] = acc[i][u];
        }
    }
    __syncthreads();

    #pragma unroll
    for (int i = 0; i < 24; i++) {
        int q = i*256 + tid;
        int row = q / 48, c4 = q % 48;
        float4 v = *(const float4*)(stage + row*192 + c4*4);
        *(float4*)(g_P + ((size_t)(b*CH + row))*KDIM + nt*192 + c4*4) = v;
    }
}

// ---------------- K2: warp-specialized D = W * P^T + fused W copy + BN stats ----------------
__device__ __forceinline__ void k2_load_stage(char* sm, const float* wsrc,
                                              const float* psrc, int c, int tp) {
    // 64 producer threads: W tile 2048 float4 + P tile 2048 float4
    #pragma unroll
    for (int i = 0; i < 32; i++) {
        int q = i*64 + tp;
        int row = q >> 4, seg = q & 15;
        cp_async16(smem_u32(sm + swz256(row, seg)),
                   wsrc + (size_t)row*KDIM + c*CHUNK + seg*4);
    }
    #pragma unroll
    for (int i = 0; i < 32; i++) {
        int q = i*64 + tp;
        int row = q >> 4, seg = q & 15;
        cp_async16(smem_u32(sm + WTILEB + swz256(row, seg)),
                   psrc + (size_t)row*KDIM + c*CHUNK + seg*4);
    }
}

__device__ __forceinline__ void k2_frags(uint32_t a[4][4], uint32_t bq[8][2],
                                         uint32_t swu, uint32_t spu, uint32_t xo,
                                         const uint32_t* offA, const uint32_t* offB) {
    #pragma unroll
    for (int mg = 0; mg < 4; mg++)
        ldmx4(a[mg], swu + (offA[mg] ^ xo));
    #pragma unroll
    for (int hh = 0; hh < 4; hh++) {
        uint32_t r[4];
        ldmx4(r, spu + (offB[hh] ^ xo));
        bq[hh*2][0] = r[0]; bq[hh*2][1] = r[1];
        bq[hh*2+1][0] = r[2]; bq[hh*2+1][1] = r[3];
    }
}

__global__ void __launch_bounds__(THR2, 1)
k2_gemm(const float* __restrict__ W, const float* __restrict__ cv1_b,
        const float* __restrict__ cv2_b, const float* __restrict__ mask,
        float* __restrict__ outW) {
    extern __shared__ char dyn2[];
    __shared__ float s_bias[CH];
    __shared__ float s_mask[MT];

    int tid = threadIdx.x;
    int wid = tid >> 5, lane = tid & 31;
    int mt = blockIdx.x, b = blockIdx.y;

    if (tid < CH) s_bias[tid] = (tid < 64) ? cv2_b[tid] : cv1_b[tid - 64];
    if (tid < MT) s_mask[tid] = mask[(size_t)b*NND + mt*MT + tid];

    const float* wsrc = W    + ((size_t)(b*NND + mt*MT))*KDIM;
    float*       wdst = outW + ((size_t)(b*NND + mt*MT))*KDIM;
    const float* psrc = g_P  + ((size_t)(b*CH))*KDIM;

    uint32_t dyn_u = smem_u32(dyn2);
    __syncthreads();   // bias/mask visible; all 192 threads participate (pre-divergence)

    if (wid >= 4) {
        // ===================== PRODUCER: 2 warps (64 threads) =====================
        int tp = tid - 128;
        // prologue: fill all 3 stages
        #pragma unroll 1
        for (int s = 0; s < STAGES; s++) {
            k2_load_stage(dyn2 + s*STAGEB, wsrc, psrc, s, tp);
            CP_COMMIT();
        }
        #pragma unroll 1
        for (int c = 0; c < NCH; c++) {
            int s = c % STAGES;
            CP_WAIT(STAGES - 1);     // chunk c landed (groups complete in order)
            MEMBAR_CTA();            // publish cp.async writes to consumer warps
            BAR_ARRIVE(1 + s);       // full(s)
            // W copy-out: de-swizzle smem -> outW (our own read of the stage)
            char* sw = dyn2 + s*STAGEB;
            #pragma unroll
            for (int i = 0; i < 32; i++) {
                int q = i*64 + tp;
                int row = q >> 4, seg = q & 15;
                float4 v = *(const float4*)(sw + swz256(row, seg));
                *(float4*)(wdst + (size_t)row*KDIM + c*CHUNK + seg*4) = v;
            }
            if (c + STAGES < NCH) {
                BAR_SYNC(4 + s);     // free(s): consumers done reading chunk c
                k2_load_stage(dyn2 + s*STAGEB, wsrc, psrc, c + STAGES, tp);
                CP_COMMIT();
            }
        }
        return;
    }

    // ===================== CONSUMER: 4 MMA warps (128 threads) =====================
    int wy = wid >> 1, wx = wid & 1;       // 2x2 grid of 64x64 tiles, full K per warp
    int g = lane >> 2, tig = lane & 3;

    // ldmatrix offsets (256B rows; k-step via ^ (ks<<5), ks 0..7)
    int mIdx = lane >> 3;
    uint32_t offA[4];
    #pragma unroll
    for (int mg = 0; mg < 4; mg++) {
        int rA = wy*64 + mg*16 + (mIdx & 1)*8 + (lane & 7);
        offA[mg] = (uint32_t)(rA*256 + ((((mIdx >> 1) ^ (rA & 7))) << 4));
    }
    uint32_t offB[4];
    #pragma unroll
    for (int hh = 0; hh < 4; hh++) {
        int ot = hh*2 + (mIdx >> 1);
        int rB = wx*64 + ot*8 + (lane & 7);
        offB[hh] = (uint32_t)(rB*256 + ((((mIdx & 1) ^ (rB & 7))) << 4));
    }

    float acc[4][8][4];
    #pragma unroll
    for (int t = 0; t < 4; t++)
        #pragma unroll
        for (int ot = 0; ot < 8; ot++)
            #pragma unroll
            for (int r = 0; r < 4; r++) acc[t][ot][r] = 0.0f;

    uint32_t A[2][4][4], Bq[2][8][2];

    #pragma unroll 1
    for (int c = 0; c < NCH; c++) {
        int s = c % STAGES;
        BAR_SYNC(1 + s);             // full(s)
        uint32_t swu = dyn_u + (uint32_t)(s*STAGEB);
        uint32_t spu = swu + WTILEB;

        k2_frags(A[0], Bq[0], swu, spu, 0u, offA, offB);
        #pragma unroll
        for (int ks = 0; ks < 7; ks++) {
            k2_frags(A[(ks+1)&1], Bq[(ks+1)&1], swu, spu, (uint32_t)((ks+1) << 5), offA, offB);
            #pragma unroll
            for (int t = 0; t < 4; t++)
                #pragma unroll
                for (int ot = 0; ot < 8; ot++)
                    mma_tf32(acc[t][ot], A[ks&1][t], Bq[ks&1][ot]);
        }
        #pragma unroll
        for (int t = 0; t < 4; t++)
            #pragma unroll
            for (int ot = 0; ot < 8; ot++)
                mma_tf32(acc[t][ot], A[1][t], Bq[1][ot]);

        BAR_ARRIVE(4 + s);           // free(s) — HMMA issue already drained frag loads
    }

    // ---- epilogue: bias + relu -> g_z; masked BN partial sums ----
    float ps1[16], ps2[16];
    #pragma unroll
    for (int i = 0; i < 16; i++) { ps1[i] = 0.0f; ps2[i] = 0.0f; }

    #pragma unroll
    for (int t = 0; t < 4; t++) {
        int m0 = wy*64 + t*16 + g;
        float mk0 = s_mask[m0], mk1 = s_mask[m0 + 8];
        #pragma unroll
        for (int ot = 0; ot < 8; ot++) {
            int o0 = wx*64 + ot*8 + 2*tig;
            float b0v = s_bias[o0], b1v = s_bias[o0+1];
            float* z0 = g_z + ((size_t)(b*CH + o0))*NND + mt*MT;
            float* z1 = z0 + NND;
            float v0 = fmaxf(acc[t][ot][0] + b0v, 0.0f);
            float v1 = fmaxf(acc[t][ot][1] + b1v, 0.0f);
            float v2 = fmaxf(acc[t][ot][2] + b0v, 0.0f);
            float v3 = fmaxf(acc[t][ot][3] + b1v, 0.0f);
            z0[m0]     = v0;
            z1[m0]     = v1;
            z0[m0 + 8] = v2;
            z1[m0 + 8] = v3;
            ps1[ot*2]   += v0*mk0 + v2*mk1;
            ps1[ot*2+1] += v1*mk0 + v3*mk1;
            ps2[ot*2]   += v0*v0*mk0 + v2*v2*mk1;
            ps2[ot*2+1] += v1*v1*mk0 + v3*v3*mk1;
        }
    }
    #pragma unroll
    for (int d = 4; d <= 16; d <<= 1) {
        #pragma unroll
        for (int i = 0; i < 16; i++) {
            ps1[i] += __shfl_xor_sync(0xFFFFFFFFu, ps1[i], d);
            ps2[i] += __shfl_xor_sync(0xFFFFFFFFu, ps2[i], d);
        }
    }
    if (g == 0) {
        int slot = (((b*16 + mt)*4) + wid)*CH;
        #pragma unroll
        for (int ot = 0; ot < 8; ot++) {
            int o0 = wx*64 + ot*8 + 2*tig;
            g_pS1[slot + o0]     = ps1[ot*2];
            g_pS1[slot + o0 + 1] = ps1[ot*2+1];
            g_pS2[slot + o0]     = ps2[ot*2];
            g_pS2[slot + o0 + 1] = ps2[ot*2+1];
        }
    }
}

// ---------------- K2c: reduce partials, finalize scale/shift ----------------
__global__ void k2c_finstats(const float* __restrict__ gamma, const float* __restrict__ beta) {
    int o = blockIdx.x;              // channel
    int tid = threadIdx.x;           // 256 threads cover 512 slots
    float s1 = g_pS1[tid*CH + o] + g_pS1[(tid + 256)*CH + o];
    float s2 = g_pS2[tid*CH + o] + g_pS2[(tid + 256)*CH + o];
    #pragma unroll
    for (int d = 16; d > 0; d >>= 1) {
        s1 += __shfl_xor_sync(0xFFFFFFFFu, s1, d);
        s2 += __shfl_xor_sync(0xFFFFFFFFu, s2, d);
    }
    __shared__ float r1[8], r2[8];
    if ((tid & 31) == 0) { r1[tid >> 5] = s1; r2[tid >> 5] = s2; }
    __syncthreads();
    if (tid == 0) {
        float t1 = 0.0f, t2 = 0.0f;
        #pragma unroll
        for (int i = 0; i < 8; i++) { t1 += r1[i]; t2 += r2[i]; }
        float total = g_misc[0], M0 = g_misc[1];
        float mean = t1 / total;
        float var = (t2 - 2.0f*mean*t1 + mean*mean*M0) / total;
        float sc = gamma[o] * rsqrtf(var + 1e-5f);
        g_scale[o] = sc;
        g_shift[o] = beta[o] - mean*sc;
    }
}

// ---------------- K3: apply BN affine + mask -> out ----------------
__global__ void __launch_bounds__(256, 8)
k3_apply(const float* __restrict__ mask, float* __restrict__ out) {
    int idx4 = blockIdx.x*256 + threadIdx.x;   // float4 index
    int row = idx4 >> 9;                       // b*128 + o
    int o = row & 127, b = row >> 7;
    int m4 = idx4 & 511;
    float4 z  = *(const float4*)(g_z + (size_t)row*NND + m4*4);
    float4 mk = __ldg((const float4*)(mask + (size_t)b*NND + m4*4));
    float sc = g_scale[o], sh = g_shift[o];
    float4 r;
    r.x = (z.x*sc + sh)*mk.x;
    r.y = (z.y*sc + sh)*mk.y;
    r.z = (z.z*sc + sh)*mk.z;
    r.w = (z.w*sc + sh)*mk.w;
    *(float4*)(out + (size_t)row*NND + m4*4) = r;
}

// ---------------- launch ----------------
extern "C" void kernel_launch(void* const* d_in, const int* in_sizes, int n_in,
                              void* d_out, int out_size) {
    (void)in_sizes; (void)n_in; (void)out_size;
    const float* X     = (const float*)d_in[0];
    const float* W     = (const float*)d_in[1];
    const float* Nb    = (const float*)d_in[2];
    const float* mask  = (const float*)d_in[3];
    const float* cv1_w = (const float*)d_in[4];
    const float* cv1_b = (const float*)d_in[5];
    const float* cv2_w = (const float*)d_in[6];
    const float* cv2_b = (const float*)d_in[7];
    const float* gamma = (const float*)d_in[8];
    const float* beta  = (const float*)d_in[9];
    float* out  = (float*)d_out;
    float* outW = out + ZN;

    cudaFuncSetAttribute(k1_gemm, cudaFuncAttributeMaxDynamicSharedMemorySize, DYN1);
    cudaFuncSetAttribute(k2_gemm, cudaFuncAttributeMaxDynamicSharedMemorySize, DYN2);

    k0_init<<<1, 256>>>(Nb, mask);                               // launch 0
    k1_gemm<<<dim3(32, 8), 256, DYN1>>>(X, cv1_w, cv2_w);        // launch 1
    k_nop<<<1, 32>>>();                                          // launch 2 (slot shim)
    k2_gemm<<<dim3(16, 8), THR2, DYN2>>>(W, cv1_b, cv2_b, mask, outW); // launch 3 <- ncu slot
    k2c_finstats<<<CH, 256>>>(gamma, beta);
    k3_apply<<<ZN/4/256, 256>>>(mask, out);
}

// round 13
// speedup vs baseline: 1.1645x; 1.1645x over previous
#include <cuda_runtime.h>
#include <cstdint>
#include <cstddef>

// ---------------- problem constants ----------------
#define BS    8
#define NFEAT 64
#define NND   2048
#define JDIM  3
#define CH    128                  // 2*NOUT
#define KDIM  6144                 // NND*JDIM
#define ZN    (BS*CH*NND)          // 2097152 zbn elements
#define CHUNK 64                   // fp32 of K per chunk (256 B per row)
#define NCH   (KDIM/CHUNK)         // 96
#define STAGES 3
#define LOOKAHEAD 2
#define MT    128                  // m-rows per CTA tile
#define WTILEB (MT*CHUNK*4)        // 32768 W tile bytes
#define PTILEB (128*CHUNK*4)       // 32768 P tile bytes
#define STAGEB (WTILEB+PTILEB)     // 65536
#define DYN2  (STAGES*STAGEB)      // 196608
#define THR2  256                  // 8 warps: 2x2 grid of 64x64 tiles, k-split pairs
#define EXST  68                   // padded row stride (floats) for pair exchange

// k1 (MMA version) smem plan
#define K1_STAGE_F (128*196)       // padded [128 o][196] stage
#define K1_CS_F    (128*64)        // C slice [128 o][64 f]
#define K1_XS_F    (64*64)         // Xt tile [64 n][64 f]
#define DYN1 ((K1_STAGE_F + 2*K1_CS_F + K1_XS_F)*4)   // 182272

// ---------------- device scratch ----------------
__device__ float g_P[(size_t)BS*CH*KDIM];   // 25.2 MB
__device__ float g_Xt[(size_t)BS*NND*NFEAT];// 4 MB transposed X: [b][n][f]
__device__ float g_z[(size_t)ZN];           // 8.4 MB
__device__ float g_pS1[256*CH];
__device__ float g_pS2[256*CH];
__device__ float g_misc[2];                 // total, M0
__device__ float g_scale[CH];
__device__ float g_shift[CH];

// ---------------- helpers ----------------
__device__ __forceinline__ uint32_t smem_u32(const void* p) {
    uint32_t a;
    asm("{ .reg .u64 t; cvta.to.shared.u64 t, %1; cvt.u32.u64 %0, t; }" : "=r"(a) : "l"(p));
    return a;
}
__device__ __forceinline__ void cp_async16(uint32_t dst, const void* src) {
    asm volatile("cp.async.cg.shared.global [%0], [%1], 16;" :: "r"(dst), "l"(src) : "memory");
}
#define CP_COMMIT() asm volatile("cp.async.commit_group;" ::: "memory")
#define CP_WAIT(n)  asm volatile("cp.async.wait_group %0;" :: "n"(n) : "memory")

__device__ __forceinline__ void mma_tf32(float* d, const uint32_t* a, const uint32_t* b) {
    asm volatile(
        "mma.sync.aligned.m16n8k8.row.col.f32.tf32.tf32.f32 "
        "{%0,%1,%2,%3}, {%4,%5,%6,%7}, {%8,%9}, {%0,%1,%2,%3};"
        : "+f"(d[0]), "+f"(d[1]), "+f"(d[2]), "+f"(d[3])
        : "r"(a[0]), "r"(a[1]), "r"(a[2]), "r"(a[3]), "r"(b[0]), "r"(b[1]));
}
__device__ __forceinline__ void ldmx4(uint32_t* r, uint32_t addr) {
    asm volatile(
        "ldmatrix.sync.aligned.m8n8.x4.shared.b16 {%0,%1,%2,%3}, [%4];"
        : "=r"(r[0]), "=r"(r[1]), "=r"(r[2]), "=r"(r[3]) : "r"(addr));
}
// 256B-row tile: seg = 16B unit 0..15; swizzle each 128B half independently
__device__ __forceinline__ int swz256(int row, int seg) {
    return row*256 + ((seg & 8) << 4) + ((((seg & 7) ^ (row & 7))) << 4);
}

// ---------------- K0: init reductions ----------------
__global__ void k0_init(const float* __restrict__ Nb, const float* __restrict__ mask) {
    int tid = threadIdx.x;
    float acc = 0.0f;
    for (int i = tid; i < BS*NND; i += 256) acc += mask[i];
    __shared__ float red[256];
    red[tid] = acc;
    __syncthreads();
    for (int s = 128; s > 0; s >>= 1) {
        if (tid < s) red[tid] += red[tid + s];
        __syncthreads();
    }
    if (tid == 0) {
        float tot = 0.0f;
        for (int i = 0; i < BS; i++) tot += Nb[i];
        g_misc[0] = tot;
        g_misc[1] = red[0];
    }
}

// ---------------- K0t: transpose X[b][f][n] -> g_Xt[b][n][f] ----------------
__global__ void k0t_transpose(const float* __restrict__ X) {
    __shared__ float t[32][33];
    int tx = threadIdx.x, ty = threadIdx.y;
    int nt = blockIdx.x, ft = blockIdx.y, b = blockIdx.z;
    #pragma unroll
    for (int i = ty; i < 32; i += 8)
        t[i][tx] = X[((size_t)(b*NFEAT + ft*32 + i))*NND + nt*32 + tx];
    __syncthreads();
    #pragma unroll
    for (int i = ty; i < 32; i += 8)
        g_Xt[((size_t)(b*NND + nt*32 + i))*NFEAT + ft*32 + tx] = t[tx][i];
}

// ---------------- K1 (MMA): P[b,o,n*3+j] = sum_f C[o, j*64+f] * X[b,f,n] ----------------
// 256 CTAs (32 n-tiles of 64 x 8 b), 256 thr (8 warps: 4 o-groups x 2 n-groups).
__global__ void __launch_bounds__(256, 1)
k1_gemm(const float* __restrict__ cv1_w, const float* __restrict__ cv2_w) {
    extern __shared__ float sm1[];
    float* stage = sm1;                        // [128 o][196]
    float* cs0   = sm1 + K1_STAGE_F;           // [128 o][64 f] swizzled
    float* cs1   = cs0 + K1_CS_F;
    float* xs    = cs1 + K1_CS_F;              // [64 n][64 f] swizzled

    int tid = threadIdx.x;
    int wid = tid >> 5, lane = tid & 31;
    int wo = wid >> 1, wn = wid & 1;
    int g = lane >> 2, tig = lane & 3;
    int mIdx = lane >> 3;
    int nt = blockIdx.x, b = blockIdx.y;

    uint32_t xs_u = smem_u32(xs);
    uint32_t cs_u0 = smem_u32(cs0);
    uint32_t cs_u1 = smem_u32(cs1);

    // stage Xt tile [64 n][64 f] swizzled
    #pragma unroll
    for (int i = 0; i < 4; i++) {
        int q = i*256 + tid;
        int n = q >> 4, seg = q & 15;
        cp_async16(xs_u + swz256(n, seg),
                   g_Xt + ((size_t)(b*NND + nt*64 + n))*NFEAT + seg*4);
    }
    // stage C slice for j=0 into cs0
    #pragma unroll
    for (int i = 0; i < 8; i++) {
        int q = i*256 + tid;
        int o = q >> 4, seg = q & 15;
        const float* src = ((o < 64) ? (cv2_w + o*192) : (cv1_w + (o-64)*192)) + seg*4;
        cp_async16(cs_u0 + swz256(o, seg), src);
    }
    CP_COMMIT();
    // stage C slice for j=1 into cs1
    #pragma unroll
    for (int i = 0; i < 8; i++) {
        int q = i*256 + tid;
        int o = q >> 4, seg = q & 15;
        const float* src = ((o < 64) ? (cv2_w + o*192) : (cv1_w + (o-64)*192)) + 64 + seg*4;
        cp_async16(cs_u1 + swz256(o, seg), src);
    }
    CP_COMMIT();

    // ldmatrix offsets (256B rows)
    uint32_t offA[2];
    #pragma unroll
    for (int t = 0; t < 2; t++) {
        int rA = wo*32 + t*16 + (mIdx & 1)*8 + (lane & 7);
        offA[t] = (uint32_t)(rA*256 + ((((mIdx >> 1) ^ (rA & 7))) << 4));
    }
    uint32_t offB[2];
    #pragma unroll
    for (int hh = 0; hh < 2; hh++) {
        int ot = hh*2 + (mIdx >> 1);
        int rB = wn*32 + ot*8 + (lane & 7);
        offB[hh] = (uint32_t)(rB*256 + ((((mIdx & 1) ^ (rB & 7))) << 4));
    }

    #pragma unroll 1
    for (int j = 0; j < JDIM; j++) {
        if (j < 2) { CP_WAIT(1); } else { CP_WAIT(0); }
        __syncthreads();
        uint32_t cu = (j == 1) ? cs_u1 : cs_u0;

        float acc[2][4][4];
        #pragma unroll
        for (int t = 0; t < 2; t++)
            #pragma unroll
            for (int ot = 0; ot < 4; ot++)
                #pragma unroll
                for (int r = 0; r < 4; r++) acc[t][ot][r] = 0.0f;

        #pragma unroll
        for (int ks = 0; ks < 8; ks++) {
            uint32_t xo = (uint32_t)(ks << 5);
            uint32_t a[2][4];
            uint32_t bq[4][2];
            #pragma unroll
            for (int t = 0; t < 2; t++)
                ldmx4(a[t], cu + (offA[t] ^ xo));
            #pragma unroll
            for (int hh = 0; hh < 2; hh++) {
                uint32_t r[4];
                ldmx4(r, xs_u + (offB[hh] ^ xo));
                bq[hh*2][0]   = r[0]; bq[hh*2][1]   = r[1];
                bq[hh*2+1][0] = r[2]; bq[hh*2+1][1] = r[3];
            }
            #pragma unroll
            for (int t = 0; t < 2; t++)
                #pragma unroll
                for (int ot = 0; ot < 4; ot++)
                    mma_tf32(acc[t][ot], a[t], bq[ot]);
        }

        // scatter into padded stage (2-way conflicts max)
        #pragma unroll
        for (int t = 0; t < 2; t++)
            #pragma unroll
            for (int ot = 0; ot < 4; ot++)
                #pragma unroll
                for (int r = 0; r < 4; r++) {
                    int o = wo*32 + t*16 + g + ((r >> 1) << 3);
                    int col = (wn*32 + ot*8 + 2*tig + (r & 1))*3 + j;
                    stage[o*196 + col] = acc[t][ot][r];
                }
        __syncthreads();

        if (j == 0) {
            // stage C slice for j=2 into cs0 (safe: cs0 fully consumed)
            #pragma unroll
            for (int i = 0; i < 8; i++) {
                int q = i*256 + tid;
                int o = q >> 4, seg = q & 15;
                const float* src = ((o < 64) ? (cv2_w + o*192) : (cv1_w + (o-64)*192)) + 128 + seg*4;
                cp_async16(cs_u0 + swz256(o, seg), src);
            }
            CP_COMMIT();
        }
    }

    // coalesced write-out: 128 rows x 48 float4
    #pragma unroll
    for (int i = 0; i < 24; i++) {
        int q = i*256 + tid;
        int row = q / 48, c4 = q % 48;
        float4 v = *(const float4*)(stage + row*196 + c4*4);
        *(float4*)(g_P + ((size_t)(b*CH + row))*KDIM + nt*192 + c4*4) = v;
    }
}

// ---------------- K2: D = W * P^T, 256B-row chunks, k-split pairs (R10 config) ----------------
__device__ __forceinline__ void k2_load_stage(char* sm, const float* wsrc,
                                              const float* psrc, int c, int tid) {
    #pragma unroll
    for (int i = 0; i < 8; i++) {
        int q = i*THR2 + tid;
        int row = q >> 4, seg = q & 15;
        cp_async16(smem_u32(sm + swz256(row, seg)),
                   wsrc + (size_t)row*KDIM + c*CHUNK + seg*4);
    }
    #pragma unroll
    for (int i = 0; i < 8; i++) {
        int q = i*THR2 + tid;
        int row = q >> 4, seg = q & 15;
        cp_async16(smem_u32(sm + WTILEB + swz256(row, seg)),
                   psrc + (size_t)row*KDIM + c*CHUNK + seg*4);
    }
}

__device__ __forceinline__ void k2_frags(uint32_t a[4][4], uint32_t bq[8][2],
                                         uint32_t swu, uint32_t spu, uint32_t xo,
                                         const uint32_t* offA, const uint32_t* offB) {
    #pragma unroll
    for (int mg = 0; mg < 4; mg++)
        ldmx4(a[mg], swu + (offA[mg] ^ xo));
    #pragma unroll
    for (int hh = 0; hh < 4; hh++) {
        uint32_t r[4];
        ldmx4(r, spu + (offB[hh] ^ xo));
        bq[hh*2][0] = r[0]; bq[hh*2][1] = r[1];
        bq[hh*2+1][0] = r[2]; bq[hh*2+1][1] = r[3];
    }
}

__global__ void __launch_bounds__(THR2, 1)
k2_gemm(const float* __restrict__ W, const float* __restrict__ cv1_b,
        const float* __restrict__ cv2_b, const float* __restrict__ mask,
        float* __restrict__ outW) {
    extern __shared__ char dyn2[];
    __shared__ float s_bias[CH];
    __shared__ float s_mask[MT];

    int tid = threadIdx.x;
    int wid = tid >> 5, lane = tid & 31;
    int p  = wid >> 1;                     // pair 0..3
    int h  = wid & 1;                      // k-half within pair
    int wy = p >> 1, wx = p & 1;           // 2x2 grid, 64x64 tiles
    int g = lane >> 2, tig = lane & 3;
    int mt = blockIdx.x, b = blockIdx.y;

    if (tid < CH) s_bias[tid] = (tid < 64) ? cv2_b[tid] : cv1_b[tid - 64];
    if (tid < MT) s_mask[tid] = mask[(size_t)b*NND + mt*MT + tid];

    const float* wsrc = W    + ((size_t)(b*NND + mt*MT))*KDIM;
    float*       wdst = outW + ((size_t)(b*NND + mt*MT))*KDIM;
    const float* psrc = g_P  + ((size_t)(b*CH))*KDIM;

    uint32_t dyn_u = smem_u32(dyn2);

    int mIdx = lane >> 3;
    uint32_t offA[4];
    #pragma unroll
    for (int mg = 0; mg < 4; mg++) {
        int rA = wy*64 + mg*16 + (mIdx & 1)*8 + (lane & 7);
        offA[mg] = (uint32_t)(rA*256 + ((((mIdx >> 1) ^ (rA & 7))) << 4));
    }
    uint32_t offB[4];
    #pragma unroll
    for (int hh = 0; hh < 4; hh++) {
        int ot = hh*2 + (mIdx >> 1);
        int rB = wx*64 + ot*8 + (lane & 7);
        offB[hh] = (uint32_t)(rB*256 + ((((mIdx & 1) ^ (rB & 7))) << 4));
    }

    float acc[4][8][4];
    #pragma unroll
    for (int t = 0; t < 4; t++)
        #pragma unroll
        for (int ot = 0; ot < 8; ot++)
            #pragma unroll
            for (int r = 0; r < 4; r++) acc[t][ot][r] = 0.0f;

    #pragma unroll
    for (int s = 0; s < LOOKAHEAD; s++) {
        k2_load_stage(dyn2 + s*STAGEB, wsrc, psrc, s, tid);
        CP_COMMIT();
    }

    uint32_t xo0 = (uint32_t)((h*4 + 0) << 5);
    uint32_t xo1 = (uint32_t)((h*4 + 1) << 5);
    uint32_t xo2 = (uint32_t)((h*4 + 2) << 5);
    uint32_t xo3 = (uint32_t)((h*4 + 3) << 5);

    for (int c = 0; c < NCH; c++) {
        CP_WAIT(LOOKAHEAD - 1);
        __syncthreads();

        uint32_t swu = dyn_u + (uint32_t)((c % STAGES)*STAGEB);
        uint32_t spu = swu + WTILEB;
        char*    sw  = dyn2 + (c % STAGES)*STAGEB;

        uint32_t a0[4][4], b0[8][2], a1[4][4], b1[8][2];

        k2_frags(a0, b0, swu, spu, xo0, offA, offB);

        if (c + LOOKAHEAD < NCH)
            k2_load_stage(dyn2 + ((c + LOOKAHEAD) % STAGES)*STAGEB, wsrc, psrc,
                          c + LOOKAHEAD, tid);
        CP_COMMIT();

        // fused W copy-out: de-swizzle smem -> outW
        #pragma unroll
        for (int i = 0; i < 8; i++) {
            int q = i*THR2 + tid;
            int row = q >> 4, seg = q & 15;
            float4 v = *(const float4*)(sw + swz256(row, seg));
            *(float4*)(wdst + (size_t)row*KDIM + c*CHUNK + seg*4) = v;
        }

        k2_frags(a1, b1, swu, spu, xo1, offA, offB);
        #pragma unroll
        for (int t = 0; t < 4; t++)
            #pragma unroll
            for (int ot = 0; ot < 8; ot++)
                mma_tf32(acc[t][ot], a0[t], b0[ot]);

        k2_frags(a0, b0, swu, spu, xo2, offA, offB);
        #pragma unroll
        for (int t = 0; t < 4; t++)
            #pragma unroll
            for (int ot = 0; ot < 8; ot++)
                mma_tf32(acc[t][ot], a1[t], b1[ot]);

        k2_frags(a1, b1, swu, spu, xo3, offA, offB);
        #pragma unroll
        for (int t = 0; t < 4; t++)
            #pragma unroll
            for (int ot = 0; ot < 8; ot++)
                mma_tf32(acc[t][ot], a0[t], b0[ot]);
        #pragma unroll
        for (int t = 0; t < 4; t++)
            #pragma unroll
            for (int ot = 0; ot < 8; ot++)
                mma_tf32(acc[t][ot], a1[t], b1[ot]);
    }

    // ---- pair merge: h=1 stores partial acc to padded smem, h=0 adds ----
    __syncthreads();
    float* ex = (float*)(dyn2) + p * (64*EXST);
    if (h == 1) {
        #pragma unroll
        for (int t = 0; t < 4; t++)
            #pragma unroll
            for (int ot = 0; ot < 8; ot++)
                #pragma unroll
                for (int r = 0; r < 4; r++) {
                    int row = t*16 + g + ((r >> 1) << 3);
                    int col = ot*8 + 2*tig + (r & 1);
                    ex[row*EXST + col] = acc[t][ot][r];
                }
    }
    __syncthreads();

    if (h == 0) {
        float ps1[16], ps2[16];
        #pragma unroll
        for (int i = 0; i < 16; i++) { ps1[i] = 0.0f; ps2[i] = 0.0f; }

        #pragma unroll
        for (int t = 0; t < 4; t++) {
            int m0 = wy*64 + t*16 + g;
            float mk0 = s_mask[m0], mk1 = s_mask[m0 + 8];
            #pragma unroll
            for (int ot = 0; ot < 8; ot++) {
                int o0 = wx*64 + ot*8 + 2*tig;
                float b0v = s_bias[o0], b1v = s_bias[o0+1];
                float* z0 = g_z + ((size_t)(b*CH + o0))*NND + mt*MT;
                float* z1 = z0 + NND;
                float v0, v1, v2, v3;
                {
                    int row0 = t*16 + g, row1 = row0 + 8;
                    int col0 = ot*8 + 2*tig, col1 = col0 + 1;
                    v0 = fmaxf(acc[t][ot][0] + ex[row0*EXST + col0] + b0v, 0.0f);
                    v1 = fmaxf(acc[t][ot][1] + ex[row0*EXST + col1] + b1v, 0.0f);
                    v2 = fmaxf(acc[t][ot][2] + ex[row1*EXST + col0] + b0v, 0.0f);
                    v3 = fmaxf(acc[t][ot][3] + ex[row1*EXST + col1] + b1v, 0.0f);
                }
                z0[m0]     = v0;
                z1[m0]     = v1;
                z0[m0 + 8] = v2;
                z1[m0 + 8] = v3;
                ps1[ot*2]   += v0*mk0 + v2*mk1;
                ps1[ot*2+1] += v1*mk0 + v3*mk1;
                ps2[ot*2]   += v0*v0*mk0 + v2*v2*mk1;
                ps2[ot*2+1] += v1*v1*mk0 + v3*v3*mk1;
            }
        }
        #pragma unroll
        for (int d = 4; d <= 16; d <<= 1) {
            #pragma unroll
            for (int i = 0; i < 16; i++) {
                ps1[i] += __shfl_xor_sync(0xFFFFFFFFu, ps1[i], d);
                ps2[i] += __shfl_xor_sync(0xFFFFFFFFu, ps2[i], d);
            }
        }
        if (g == 0) {
            int slot = ((b*16 + mt)*2 + wy)*CH;
            #pragma unroll
            for (int ot = 0; ot < 8; ot++) {
                int o0 = wx*64 + ot*8 + 2*tig;
                g_pS1[slot + o0]     = ps1[ot*2];
                g_pS1[slot + o0 + 1] = ps1[ot*2+1];
                g_pS2[slot + o0]     = ps2[ot*2];
                g_pS2[slot + o0 + 1] = ps2[ot*2+1];
            }
        }
    }
}

// ---------------- K2c: reduce partials, finalize scale/shift ----------------
__global__ void k2c_finstats(const float* __restrict__ gamma, const float* __restrict__ beta) {
    int o = blockIdx.x;              // channel
    int tid = threadIdx.x;           // 256 partial slots
    float s1 = g_pS1[tid*CH + o];
    float s2 = g_pS2[tid*CH + o];
    #pragma unroll
    for (int d = 16; d > 0; d >>= 1) {
        s1 += __shfl_xor_sync(0xFFFFFFFFu, s1, d);
        s2 += __shfl_xor_sync(0xFFFFFFFFu, s2, d);
    }
    __shared__ float r1[8], r2[8];
    if ((tid & 31) == 0) { r1[tid >> 5] = s1; r2[tid >> 5] = s2; }
    __syncthreads();
    if (tid == 0) {
        float t1 = 0.0f, t2 = 0.0f;
        #pragma unroll
        for (int i = 0; i < 8; i++) { t1 += r1[i]; t2 += r2[i]; }
        float total = g_misc[0], M0 = g_misc[1];
        float mean = t1 / total;
        float var = (t2 - 2.0f*mean*t1 + mean*mean*M0) / total;
        float sc = gamma[o] * rsqrtf(var + 1e-5f);
        g_scale[o] = sc;
        g_shift[o] = beta[o] - mean*sc;
    }
}

// ---------------- K3: apply BN affine + mask -> out ----------------
__global__ void __launch_bounds__(256, 8)
k3_apply(const float* __restrict__ mask, float* __restrict__ out) {
    int idx4 = blockIdx.x*256 + threadIdx.x;   // float4 index
    int row = idx4 >> 9;                       // b*128 + o
    int o = row & 127, b = row >> 7;
    int m4 = idx4 & 511;
    float4 z  = *(const float4*)(g_z + (size_t)row*NND + m4*4);
    float4 mk = __ldg((const float4*)(mask + (size_t)b*NND + m4*4));
    float sc = g_scale[o], sh = g_shift[o];
    float4 r;
    r.x = (z.x*sc + sh)*mk.x;
    r.y = (z.y*sc + sh)*mk.y;
    r.z = (z.z*sc + sh)*mk.z;
    r.w = (z.w*sc + sh)*mk.w;
    *(float4*)(out + (size_t)row*NND + m4*4) = r;
}

// ---------------- launch ----------------
extern "C" void kernel_launch(void* const* d_in, const int* in_sizes, int n_in,
                              void* d_out, int out_size) {
    (void)in_sizes; (void)n_in; (void)out_size;
    const float* X     = (const float*)d_in[0];
    const float* W     = (const float*)d_in[1];
    const float* Nb    = (const float*)d_in[2];
    const float* mask  = (const float*)d_in[3];
    const float* cv1_w = (const float*)d_in[4];
    const float* cv1_b = (const float*)d_in[5];
    const float* cv2_w = (const float*)d_in[6];
    const float* cv2_b = (const float*)d_in[7];
    const float* gamma = (const float*)d_in[8];
    const float* beta  = (const float*)d_in[9];
    float* out  = (float*)d_out;
    float* outW = out + ZN;

    cudaFuncSetAttribute(k1_gemm, cudaFuncAttributeMaxDynamicSharedMemorySize, DYN1);
    cudaFuncSetAttribute(k2_gemm, cudaFuncAttributeMaxDynamicSharedMemorySize, DYN2);

    k0_init<<<1, 256>>>(Nb, mask);                               // launch 0
    k0t_transpose<<<dim3(64, 2, 8), dim3(32, 8)>>>(X);           // launch 1
    k1_gemm<<<dim3(32, 8), 256, DYN1>>>(cv1_w, cv2_w);           // launch 2
    k2_gemm<<<dim3(16, 8), THR2, DYN2>>>(W, cv1_b, cv2_b, mask, outW); // launch 3 <- ncu slot
    k2c_finstats<<<CH, 256>>>(gamma, beta);
    k3_apply<<<ZN/4/256, 256>>>(mask, out);
}

// round 14
// speedup vs baseline: 1.1673x; 1.0024x over previous
#include <cuda_runtime.h>
#include <cstdint>
#include <cstddef>

// ---------------- problem constants ----------------
#define BS    8
#define NFEAT 64
#define NND   2048
#define JDIM  3
#define CH    128                  // 2*NOUT
#define KDIM  6144                 // NND*JDIM
#define ZN    (BS*CH*NND)          // 2097152 zbn elements
#define CHUNK 64                   // fp32 of K per chunk (256 B per row)
#define NCH   (KDIM/CHUNK)         // 96
#define NTILE 128                  // (b,mt) tiles
#define UNITS (NTILE*NCH)          // 12288
#define NCTA2 148
#define STAGES 3
#define LOOKAHEAD 2
#define MT    128                  // m-rows per tile
#define WTILEB (MT*CHUNK*4)        // 32768
#define PTILEB (128*CHUNK*4)       // 32768
#define STAGEB (WTILEB+PTILEB)     // 65536
#define DYN2  (STAGES*STAGEB)      // 196608
#define THR2  256

// k1 smem plan
#define K1_STAGE_F (128*196)
#define K1_CS_F    (128*64)
#define K1_XS_F    (64*64)
#define DYN1 ((K1_STAGE_F + 2*K1_CS_F + K1_XS_F)*4)   // 182272

// k2e smem: padded D tile [128][129] + mask[128]
#define DYNE ((128*129 + 128)*4)   // 66560

// ---------------- device scratch ----------------
__device__ float g_P[(size_t)BS*CH*KDIM];   // 25.2 MB
__device__ float g_Xt[(size_t)BS*NND*NFEAT];// 4 MB
__device__ float g_D[(size_t)NTILE*MT*CH];  // 8 MB partial D
__device__ float g_z[(size_t)ZN];           // 8.4 MB
__device__ float g_pS1[NTILE*CH];
__device__ float g_pS2[NTILE*CH];
__device__ float g_misc[2];
__device__ float g_scale[CH];
__device__ float g_shift[CH];

// ---------------- helpers ----------------
__device__ __forceinline__ uint32_t smem_u32(const void* p) {
    uint32_t a;
    asm("{ .reg .u64 t; cvta.to.shared.u64 t, %1; cvt.u32.u64 %0, t; }" : "=r"(a) : "l"(p));
    return a;
}
__device__ __forceinline__ void cp_async16(uint32_t dst, const void* src) {
    asm volatile("cp.async.cg.shared.global [%0], [%1], 16;" :: "r"(dst), "l"(src) : "memory");
}
#define CP_COMMIT() asm volatile("cp.async.commit_group;" ::: "memory")
#define CP_WAIT(n)  asm volatile("cp.async.wait_group %0;" :: "n"(n) : "memory")

__device__ __forceinline__ void mma_tf32(float* d, const uint32_t* a, const uint32_t* b) {
    asm volatile(
        "mma.sync.aligned.m16n8k8.row.col.f32.tf32.tf32.f32 "
        "{%0,%1,%2,%3}, {%4,%5,%6,%7}, {%8,%9}, {%0,%1,%2,%3};"
        : "+f"(d[0]), "+f"(d[1]), "+f"(d[2]), "+f"(d[3])
        : "r"(a[0]), "r"(a[1]), "r"(a[2]), "r"(a[3]), "r"(b[0]), "r"(b[1]));
}
__device__ __forceinline__ void ldmx4(uint32_t* r, uint32_t addr) {
    asm volatile(
        "ldmatrix.sync.aligned.m8n8.x4.shared.b16 {%0,%1,%2,%3}, [%4];"
        : "=r"(r[0]), "=r"(r[1]), "=r"(r[2]), "=r"(r[3]) : "r"(addr));
}
__device__ __forceinline__ int swz256(int row, int seg) {
    return row*256 + ((seg & 8) << 4) + ((((seg & 7) ^ (row & 7))) << 4);
}

// ---------------- K0: init reductions ----------------
__global__ void k0_init(const float* __restrict__ Nb, const float* __restrict__ mask) {
    int tid = threadIdx.x;
    float acc = 0.0f;
    for (int i = tid; i < BS*NND; i += 256) acc += mask[i];
    __shared__ float red[256];
    red[tid] = acc;
    __syncthreads();
    for (int s = 128; s > 0; s >>= 1) {
        if (tid < s) red[tid] += red[tid + s];
        __syncthreads();
    }
    if (tid == 0) {
        float tot = 0.0f;
        for (int i = 0; i < BS; i++) tot += Nb[i];
        g_misc[0] = tot;
        g_misc[1] = red[0];
    }
}

// ---------------- K0t: transpose X + zero g_D ----------------
__global__ void k0t_transpose(const float* __restrict__ X) {
    __shared__ float t[32][33];
    int tx = threadIdx.x, ty = threadIdx.y;
    int nt = blockIdx.x, ft = blockIdx.y, b = blockIdx.z;
    #pragma unroll
    for (int i = ty; i < 32; i += 8)
        t[i][tx] = X[((size_t)(b*NFEAT + ft*32 + i))*NND + nt*32 + tx];
    __syncthreads();
    #pragma unroll
    for (int i = ty; i < 32; i += 8)
        g_Xt[((size_t)(b*NND + nt*32 + i))*NFEAT + ft*32 + tx] = t[tx][i];
    // zero g_D: 1024 blocks x 256 thr x 2 float4 = 2M floats
    int lin = (blockIdx.z*2 + blockIdx.y)*64 + blockIdx.x;
    int tidf = lin*256 + ty*32 + tx;
    float4 zz = make_float4(0.f, 0.f, 0.f, 0.f);
    *(float4*)(g_D + (size_t)tidf*8)     = zz;
    *(float4*)(g_D + (size_t)tidf*8 + 4) = zz;
}

// ---------------- K1 (MMA): P[b,o,n*3+j] = sum_f C[o, j*64+f] * X[b,f,n] ----------------
__global__ void __launch_bounds__(256, 1)
k1_gemm(const float* __restrict__ cv1_w, const float* __restrict__ cv2_w) {
    extern __shared__ float sm1[];
    float* stage = sm1;                        // [128 o][196]
    float* cs0   = sm1 + K1_STAGE_F;
    float* cs1   = cs0 + K1_CS_F;
    float* xs    = cs1 + K1_CS_F;

    int tid = threadIdx.x;
    int wid = tid >> 5, lane = tid & 31;
    int wo = wid >> 1, wn = wid & 1;
    int g = lane >> 2, tig = lane & 3;
    int mIdx = lane >> 3;
    int nt = blockIdx.x, b = blockIdx.y;

    uint32_t xs_u = smem_u32(xs);
    uint32_t cs_u0 = smem_u32(cs0);
    uint32_t cs_u1 = smem_u32(cs1);

    #pragma unroll
    for (int i = 0; i < 4; i++) {
        int q = i*256 + tid;
        int n = q >> 4, seg = q & 15;
        cp_async16(xs_u + swz256(n, seg),
                   g_Xt + ((size_t)(b*NND + nt*64 + n))*NFEAT + seg*4);
    }
    #pragma unroll
    for (int i = 0; i < 8; i++) {
        int q = i*256 + tid;
        int o = q >> 4, seg = q & 15;
        const float* src = ((o < 64) ? (cv2_w + o*192) : (cv1_w + (o-64)*192)) + seg*4;
        cp_async16(cs_u0 + swz256(o, seg), src);
    }
    CP_COMMIT();
    #pragma unroll
    for (int i = 0; i < 8; i++) {
        int q = i*256 + tid;
        int o = q >> 4, seg = q & 15;
        const float* src = ((o < 64) ? (cv2_w + o*192) : (cv1_w + (o-64)*192)) + 64 + seg*4;
        cp_async16(cs_u1 + swz256(o, seg), src);
    }
    CP_COMMIT();

    uint32_t offA[2];
    #pragma unroll
    for (int t = 0; t < 2; t++) {
        int rA = wo*32 + t*16 + (mIdx & 1)*8 + (lane & 7);
        offA[t] = (uint32_t)(rA*256 + ((((mIdx >> 1) ^ (rA & 7))) << 4));
    }
    uint32_t offB[2];
    #pragma unroll
    for (int hh = 0; hh < 2; hh++) {
        int ot = hh*2 + (mIdx >> 1);
        int rB = wn*32 + ot*8 + (lane & 7);
        offB[hh] = (uint32_t)(rB*256 + ((((mIdx & 1) ^ (rB & 7))) << 4));
    }

    #pragma unroll 1
    for (int j = 0; j < JDIM; j++) {
        if (j < 2) { CP_WAIT(1); } else { CP_WAIT(0); }
        __syncthreads();
        uint32_t cu = (j == 1) ? cs_u1 : cs_u0;

        float acc[2][4][4];
        #pragma unroll
        for (int t = 0; t < 2; t++)
            #pragma unroll
            for (int ot = 0; ot < 4; ot++)
                #pragma unroll
                for (int r = 0; r < 4; r++) acc[t][ot][r] = 0.0f;

        #pragma unroll
        for (int ks = 0; ks < 8; ks++) {
            uint32_t xo = (uint32_t)(ks << 5);
            uint32_t a[2][4];
            uint32_t bq[4][2];
            #pragma unroll
            for (int t = 0; t < 2; t++)
                ldmx4(a[t], cu + (offA[t] ^ xo));
            #pragma unroll
            for (int hh = 0; hh < 2; hh++) {
                uint32_t r[4];
                ldmx4(r, xs_u + (offB[hh] ^ xo));
                bq[hh*2][0]   = r[0]; bq[hh*2][1]   = r[1];
                bq[hh*2+1][0] = r[2]; bq[hh*2+1][1] = r[3];
            }
            #pragma unroll
            for (int t = 0; t < 2; t++)
                #pragma unroll
                for (int ot = 0; ot < 4; ot++)
                    mma_tf32(acc[t][ot], a[t], bq[ot]);
        }

        #pragma unroll
        for (int t = 0; t < 2; t++)
            #pragma unroll
            for (int ot = 0; ot < 4; ot++)
                #pragma unroll
                for (int r = 0; r < 4; r++) {
                    int o = wo*32 + t*16 + g + ((r >> 1) << 3);
                    int col = (wn*32 + ot*8 + 2*tig + (r & 1))*3 + j;
                    stage[o*196 + col] = acc[t][ot][r];
                }
        __syncthreads();

        if (j == 0) {
            #pragma unroll
            for (int i = 0; i < 8; i++) {
                int q = i*256 + tid;
                int o = q >> 4, seg = q & 15;
                const float* src = ((o < 64) ? (cv2_w + o*192) : (cv1_w + (o-64)*192)) + 128 + seg*4;
                cp_async16(cs_u0 + swz256(o, seg), src);
            }
            CP_COMMIT();
        }
    }

    #pragma unroll
    for (int i = 0; i < 24; i++) {
        int q = i*256 + tid;
        int row = q / 48, c4 = q % 48;
        float4 v = *(const float4*)(stage + row*196 + c4*4);
        *(float4*)(g_P + ((size_t)(b*CH + row))*KDIM + nt*192 + c4*4) = v;
    }
}

// ---------------- K2: persistent D = W * P^T over 148 CTAs, fused W copy ----------------
__device__ __forceinline__ void k2_load_stage(char* sm, int u, int tid,
                                              const float* W, const float* P) {
    int tile = u / NCH, c = u % NCH;
    int b = tile >> 4, mt = tile & 15;
    const float* wsrc = W   + ((size_t)(b*NND + mt*MT))*KDIM + c*CHUNK;
    const float* psrc = g_P + ((size_t)(b*CH))*KDIM + c*CHUNK;
    #pragma unroll
    for (int i = 0; i < 8; i++) {
        int q = i*THR2 + tid;
        int row = q >> 4, seg = q & 15;
        cp_async16(smem_u32(sm + swz256(row, seg)), wsrc + (size_t)row*KDIM + seg*4);
    }
    #pragma unroll
    for (int i = 0; i < 8; i++) {
        int q = i*THR2 + tid;
        int row = q >> 4, seg = q & 15;
        cp_async16(smem_u32(sm + WTILEB + swz256(row, seg)), psrc + (size_t)row*KDIM + seg*4);
    }
}

__device__ __forceinline__ void k2_frags(uint32_t a[4][4], uint32_t bq[8][2],
                                         uint32_t swu, uint32_t spu, uint32_t xo,
                                         const uint32_t* offA, const uint32_t* offB) {
    #pragma unroll
    for (int mg = 0; mg < 4; mg++)
        ldmx4(a[mg], swu + (offA[mg] ^ xo));
    #pragma unroll
    for (int hh = 0; hh < 4; hh++) {
        uint32_t r[4];
        ldmx4(r, spu + (offB[hh] ^ xo));
        bq[hh*2][0] = r[0]; bq[hh*2][1] = r[1];
        bq[hh*2+1][0] = r[2]; bq[hh*2+1][1] = r[3];
    }
}

__global__ void __launch_bounds__(THR2, 1)
k2_gemm(const float* __restrict__ W, float* __restrict__ outW) {
    extern __shared__ char dyn2[];

    int tid = threadIdx.x;
    int wid = tid >> 5, lane = tid & 31;
    int p  = wid >> 1;
    int h  = wid & 1;
    int wy = p >> 1, wx = p & 1;
    int g = lane >> 2, tig = lane & 3;

    int cta = blockIdx.x;
    const int base = UNITS / NCTA2;            // 83
    const int rem  = UNITS % NCTA2;            // 4
    int start = cta*base + (cta < rem ? cta : rem);
    int end   = start + base + (cta < rem ? 1 : 0);

    uint32_t dyn_u = smem_u32(dyn2);

    int mIdx = lane >> 3;
    uint32_t offA[4];
    #pragma unroll
    for (int mg = 0; mg < 4; mg++) {
        int rA = wy*64 + mg*16 + (mIdx & 1)*8 + (lane & 7);
        offA[mg] = (uint32_t)(rA*256 + ((((mIdx >> 1) ^ (rA & 7))) << 4));
    }
    uint32_t offB[4];
    #pragma unroll
    for (int hh = 0; hh < 4; hh++) {
        int ot = hh*2 + (mIdx >> 1);
        int rB = wx*64 + ot*8 + (lane & 7);
        offB[hh] = (uint32_t)(rB*256 + ((((mIdx & 1) ^ (rB & 7))) << 4));
    }

    float acc[4][8][4];
    #pragma unroll
    for (int t = 0; t < 4; t++)
        #pragma unroll
        for (int ot = 0; ot < 8; ot++)
            #pragma unroll
            for (int r = 0; r < 4; r++) acc[t][ot][r] = 0.0f;

    #pragma unroll
    for (int s = 0; s < LOOKAHEAD; s++) {
        k2_load_stage(dyn2 + s*STAGEB, start + s, tid, W, g_P);
        CP_COMMIT();
    }

    uint32_t xo0 = (uint32_t)((h*4 + 0) << 5);
    uint32_t xo1 = (uint32_t)((h*4 + 1) << 5);
    uint32_t xo2 = (uint32_t)((h*4 + 2) << 5);
    uint32_t xo3 = (uint32_t)((h*4 + 3) << 5);

    for (int u = start; u < end; u++) {
        int it = u - start;
        int tile = u / NCH, c = u % NCH;
        int b = tile >> 4, mt = tile & 15;

        CP_WAIT(LOOKAHEAD - 1);
        __syncthreads();

        uint32_t swu = dyn_u + (uint32_t)((it % STAGES)*STAGEB);
        uint32_t spu = swu + WTILEB;
        char*    sw  = dyn2 + (it % STAGES)*STAGEB;

        uint32_t a0[4][4], b0[8][2], a1[4][4], b1[8][2];

        k2_frags(a0, b0, swu, spu, xo0, offA, offB);

        if (u + LOOKAHEAD < end)
            k2_load_stage(dyn2 + ((it + LOOKAHEAD) % STAGES)*STAGEB,
                          u + LOOKAHEAD, tid, W, g_P);
        CP_COMMIT();

        // fused W copy-out
        float* wdst = outW + ((size_t)(b*NND + mt*MT))*KDIM + c*CHUNK;
        #pragma unroll
        for (int i = 0; i < 8; i++) {
            int q = i*THR2 + tid;
            int row = q >> 4, seg = q & 15;
            float4 v = *(const float4*)(sw + swz256(row, seg));
            *(float4*)(wdst + (size_t)row*KDIM + seg*4) = v;
        }

        k2_frags(a1, b1, swu, spu, xo1, offA, offB);
        #pragma unroll
        for (int t = 0; t < 4; t++)
            #pragma unroll
            for (int ot = 0; ot < 8; ot++)
                mma_tf32(acc[t][ot], a0[t], b0[ot]);

        k2_frags(a0, b0, swu, spu, xo2, offA, offB);
        #pragma unroll
        for (int t = 0; t < 4; t++)
            #pragma unroll
            for (int ot = 0; ot < 8; ot++)
                mma_tf32(acc[t][ot], a1[t], b1[ot]);

        k2_frags(a1, b1, swu, spu, xo3, offA, offB);
        #pragma unroll
        for (int t = 0; t < 4; t++)
            #pragma unroll
            for (int ot = 0; ot < 8; ot++)
                mma_tf32(acc[t][ot], a0[t], b0[ot]);
        #pragma unroll
        for (int t = 0; t < 4; t++)
            #pragma unroll
            for (int ot = 0; ot < 8; ot++)
                mma_tf32(acc[t][ot], a1[t], b1[ot]);

        // flush partial D at tile boundary / range end
        if (c == NCH - 1 || u + 1 == end) {
            float* dtile = g_D + (size_t)tile*MT*CH;
            #pragma unroll
            for (int t = 0; t < 4; t++) {
                #pragma unroll
                for (int ot = 0; ot < 8; ot++) {
                    #pragma unroll
                    for (int r = 0; r < 4; r++) {
                        int m = wy*64 + t*16 + g + ((r >> 1) << 3);
                        int o = wx*64 + ot*8 + 2*tig + (r & 1);
                        atomicAdd(&dtile[m*CH + o], acc[t][ot][r]);
                        acc[t][ot][r] = 0.0f;
                    }
                }
            }
        }
    }
}

// ---------------- K2e: epilogue — bias+relu, z write (m-contiguous), stats ----------------
__global__ void __launch_bounds__(256, 1)
k2e_epilogue(const float* __restrict__ cv1_b, const float* __restrict__ cv2_b,
             const float* __restrict__ mask) {
    extern __shared__ float sme[];
    float* sd = sme;                 // [128 m][129]
    float* sm = sme + 128*129;       // mask[128]
    int tid = threadIdx.x;
    int tile = blockIdx.x;
    int b = tile >> 4, mt = tile & 15;

    const float* dsrc = g_D + (size_t)tile*MT*CH;
    #pragma unroll
    for (int i = 0; i < 16; i++) {
        int q = i*256 + tid;             // float4 index in tile
        int m = q >> 5, o4 = q & 31;
        float4 v = *(const float4*)(dsrc + m*CH + o4*4);
        float* dst = sd + m*129 + o4*4;
        dst[0] = v.x; dst[1] = v.y; dst[2] = v.z; dst[3] = v.w;
    }
    if (tid < 128) sm[tid] = mask[(size_t)b*NND + mt*128 + tid];
    __syncthreads();

    int o = tid >> 1, half = tid & 1;
    int m0 = half*64;
    float bias = (o < 64) ? cv2_b[o] : cv1_b[o - 64];
    float s1 = 0.0f, s2 = 0.0f;
    float vals[64];
    #pragma unroll
    for (int m = 0; m < 64; m++) {
        float v = fmaxf(sd[(m0 + m)*129 + o] + bias, 0.0f);
        vals[m] = v;
        float mk = sm[m0 + m];
        s1 += v*mk;
        s2 += v*v*mk;
    }
    float* zp = g_z + ((size_t)(b*CH + o))*NND + mt*128 + m0;
    #pragma unroll
    for (int i = 0; i < 16; i++) {
        float4 v = make_float4(vals[i*4], vals[i*4+1], vals[i*4+2], vals[i*4+3]);
        *(float4*)(zp + i*4) = v;
    }
    s1 += __shfl_xor_sync(0xFFFFFFFFu, s1, 1);
    s2 += __shfl_xor_sync(0xFFFFFFFFu, s2, 1);
    if (half == 0) {
        g_pS1[tile*CH + o] = s1;
        g_pS2[tile*CH + o] = s2;
    }
}

// ---------------- K2c: reduce partials, finalize scale/shift ----------------
__global__ void k2c_finstats(const float* __restrict__ gamma, const float* __restrict__ beta) {
    int o = blockIdx.x;
    int tid = threadIdx.x;               // 128 slots
    float s1 = g_pS1[tid*CH + o];
    float s2 = g_pS2[tid*CH + o];
    #pragma unroll
    for (int d = 16; d > 0; d >>= 1) {
        s1 += __shfl_xor_sync(0xFFFFFFFFu, s1, d);
        s2 += __shfl_xor_sync(0xFFFFFFFFu, s2, d);
    }
    __shared__ float r1[4], r2[4];
    if ((tid & 31) == 0) { r1[tid >> 5] = s1; r2[tid >> 5] = s2; }
    __syncthreads();
    if (tid == 0) {
        float t1 = 0.0f, t2 = 0.0f;
        #pragma unroll
        for (int i = 0; i < 4; i++) { t1 += r1[i]; t2 += r2[i]; }
        float total = g_misc[0], M0 = g_misc[1];
        float mean = t1 / total;
        float var = (t2 - 2.0f*mean*t1 + mean*mean*M0) / total;
        float sc = gamma[o] * rsqrtf(var + 1e-5f);
        g_scale[o] = sc;
        g_shift[o] = beta[o] - mean*sc;
    }
}

// ---------------- K3: apply BN affine + mask -> out ----------------
__global__ void __launch_bounds__(256, 8)
k3_apply(const float* __restrict__ mask, float* __restrict__ out) {
    int idx4 = blockIdx.x*256 + threadIdx.x;
    int row = idx4 >> 9;
    int o = row & 127, b = row >> 7;
    int m4 = idx4 & 511;
    float4 z  = *(const float4*)(g_z + (size_t)row*NND + m4*4);
    float4 mk = __ldg((const float4*)(mask + (size_t)b*NND + m4*4));
    float sc = g_scale[o], sh = g_shift[o];
    float4 r;
    r.x = (z.x*sc + sh)*mk.x;
    r.y = (z.y*sc + sh)*mk.y;
    r.z = (z.z*sc + sh)*mk.z;
    r.w = (z.w*sc + sh)*mk.w;
    *(float4*)(out + (size_t)row*NND + m4*4) = r;
}

// ---------------- launch ----------------
extern "C" void kernel_launch(void* const* d_in, const int* in_sizes, int n_in,
                              void* d_out, int out_size) {
    (void)in_sizes; (void)n_in; (void)out_size;
    const float* X     = (const float*)d_in[0];
    const float* W     = (const float*)d_in[1];
    const float* Nb    = (const float*)d_in[2];
    const float* mask  = (const float*)d_in[3];
    const float* cv1_w = (const float*)d_in[4];
    const float* cv1_b = (const float*)d_in[5];
    const float* cv2_w = (const float*)d_in[6];
    const float* cv2_b = (const float*)d_in[7];
    const float* gamma = (const float*)d_in[8];
    const float* beta  = (const float*)d_in[9];
    float* out  = (float*)d_out;
    float* outW = out + ZN;

    cudaFuncSetAttribute(k1_gemm, cudaFuncAttributeMaxDynamicSharedMemorySize, DYN1);
    cudaFuncSetAttribute(k2_gemm, cudaFuncAttributeMaxDynamicSharedMemorySize, DYN2);
    cudaFuncSetAttribute(k2e_epilogue, cudaFuncAttributeMaxDynamicSharedMemorySize, DYNE);

    k0_init<<<1, 256>>>(Nb, mask);                               // launch 0
    k0t_transpose<<<dim3(64, 2, 8), dim3(32, 8)>>>(X);           // launch 1 (+ zero g_D)
    k1_gemm<<<dim3(32, 8), 256, DYN1>>>(cv1_w, cv2_w);           // launch 2
    k2_gemm<<<NCTA2, THR2, DYN2>>>(W, outW);                     // launch 3 <- ncu slot
    k2e_epilogue<<<NTILE, 256, DYNE>>>(cv1_b, cv2_b, mask);      // launch 4
    k2c_finstats<<<CH, 128>>>(gamma, beta);                      // launch 5
    k3_apply<<<ZN/4/256, 256>>>(mask, out);                      // launch 6
}

// round 15
// speedup vs baseline: 1.1772x; 1.0085x over previous
#include <cuda_runtime.h>
#include <cstdint>
#include <cstddef>

// ---------------- problem constants ----------------
#define BS    8
#define NFEAT 64
#define NND   2048
#define JDIM  3
#define CH    128                  // 2*NOUT
#define KDIM  6144                 // NND*JDIM
#define ZN    (BS*CH*NND)          // 2097152 zbn elements
#define CHUNK 64                   // fp32 of K per chunk (256 B per row)
#define NCH   (KDIM/CHUNK)         // 96
#define NTILE 128                  // (b,mt) tiles
#define UNITS (NTILE*NCH)          // 12288
#define NCTA2 148
#define STAGES 3
#define LOOKAHEAD 2
#define MT    128                  // m-rows per tile
#define WTILEB (MT*CHUNK*4)        // 32768
#define PTILEB (128*CHUNK*4)       // 32768
#define STAGEB (WTILEB+PTILEB)     // 65536
#define DYN2  (STAGES*STAGEB)      // 196608
#define THR2  256

// k1 smem plan
#define K1_STAGE_F (128*196)
#define K1_CS_F    (128*64)
#define K1_XS_F    (64*64)
#define DYN1 ((K1_STAGE_F + 2*K1_CS_F + K1_XS_F)*4)   // 182272

// k2e/k3 smem: padded D tile [128][129] + mask[128]
#define DYNE ((128*129 + 128)*4)   // 66560

// ---------------- device scratch ----------------
__device__ float g_P[(size_t)BS*CH*KDIM];   // 25.2 MB
__device__ float g_Xt[(size_t)BS*NND*NFEAT];// 4 MB
__device__ float g_D[(size_t)NTILE*MT*CH];  // 8 MB partial D
__device__ float g_pS1[NTILE*CH];
__device__ float g_pS2[NTILE*CH];
__device__ float g_misc[2];                 // [0] unused, [1] = M0 (atomic)
__device__ float g_scale[CH];
__device__ float g_shift[CH];

// ---------------- helpers ----------------
__device__ __forceinline__ uint32_t smem_u32(const void* p) {
    uint32_t a;
    asm("{ .reg .u64 t; cvta.to.shared.u64 t, %1; cvt.u32.u64 %0, t; }" : "=r"(a) : "l"(p));
    return a;
}
__device__ __forceinline__ void cp_async16(uint32_t dst, const void* src) {
    asm volatile("cp.async.cg.shared.global [%0], [%1], 16;" :: "r"(dst), "l"(src) : "memory");
}
#define CP_COMMIT() asm volatile("cp.async.commit_group;" ::: "memory")
#define CP_WAIT(n)  asm volatile("cp.async.wait_group %0;" :: "n"(n) : "memory")

__device__ __forceinline__ void stg16_cs(float* p, float4 v) {
    asm volatile("st.global.cs.v4.f32 [%0], {%1,%2,%3,%4};"
                 :: "l"(p), "f"(v.x), "f"(v.y), "f"(v.z), "f"(v.w) : "memory");
}

__device__ __forceinline__ void mma_tf32(float* d, const uint32_t* a, const uint32_t* b) {
    asm volatile(
        "mma.sync.aligned.m16n8k8.row.col.f32.tf32.tf32.f32 "
        "{%0,%1,%2,%3}, {%4,%5,%6,%7}, {%8,%9}, {%0,%1,%2,%3};"
        : "+f"(d[0]), "+f"(d[1]), "+f"(d[2]), "+f"(d[3])
        : "r"(a[0]), "r"(a[1]), "r"(a[2]), "r"(a[3]), "r"(b[0]), "r"(b[1]));
}
__device__ __forceinline__ void ldmx4(uint32_t* r, uint32_t addr) {
    asm volatile(
        "ldmatrix.sync.aligned.m8n8.x4.shared.b16 {%0,%1,%2,%3}, [%4];"
        : "=r"(r[0]), "=r"(r[1]), "=r"(r[2]), "=r"(r[3]) : "r"(addr));
}
__device__ __forceinline__ int swz256(int row, int seg) {
    return row*256 + ((seg & 8) << 4) + ((((seg & 7) ^ (row & 7))) << 4);
}

// ---------------- dummy kernel: keeps k2 in the ncu capture slot ----------------
__global__ void k_nop() {}

// ---------------- K0t: transpose X + zero g_D + zero g_misc ----------------
__global__ void k0t_transpose(const float* __restrict__ X) {
    __shared__ float t[32][33];
    int tx = threadIdx.x, ty = threadIdx.y;
    int nt = blockIdx.x, ft = blockIdx.y, b = blockIdx.z;
    #pragma unroll
    for (int i = ty; i < 32; i += 8)
        t[i][tx] = X[((size_t)(b*NFEAT + ft*32 + i))*NND + nt*32 + tx];
    __syncthreads();
    #pragma unroll
    for (int i = ty; i < 32; i += 8)
        g_Xt[((size_t)(b*NND + nt*32 + i))*NFEAT + ft*32 + tx] = t[tx][i];
    // zero g_D: 1024 blocks x 256 thr x 2 float4 = 2M floats
    int lin = (blockIdx.z*2 + blockIdx.y)*64 + blockIdx.x;
    int tidf = lin*256 + ty*32 + tx;
    float4 zz = make_float4(0.f, 0.f, 0.f, 0.f);
    *(float4*)(g_D + (size_t)tidf*8)     = zz;
    *(float4*)(g_D + (size_t)tidf*8 + 4) = zz;
    if (tidf == 0) { g_misc[0] = 0.f; g_misc[1] = 0.f; }
}

// ---------------- K1 (MMA): P[b,o,n*3+j] = sum_f C[o, j*64+f] * X[b,f,n] ----------------
__global__ void __launch_bounds__(256, 1)
k1_gemm(const float* __restrict__ cv1_w, const float* __restrict__ cv2_w) {
    extern __shared__ float sm1[];
    float* stage = sm1;                        // [128 o][196]
    float* cs0   = sm1 + K1_STAGE_F;
    float* cs1   = cs0 + K1_CS_F;
    float* xs    = cs1 + K1_CS_F;

    int tid = threadIdx.x;
    int wid = tid >> 5, lane = tid & 31;
    int wo = wid >> 1, wn = wid & 1;
    int g = lane >> 2, tig = lane & 3;
    int mIdx = lane >> 3;
    int nt = blockIdx.x, b = blockIdx.y;

    uint32_t xs_u = smem_u32(xs);
    uint32_t cs_u0 = smem_u32(cs0);
    uint32_t cs_u1 = smem_u32(cs1);

    #pragma unroll
    for (int i = 0; i < 4; i++) {
        int q = i*256 + tid;
        int n = q >> 4, seg = q & 15;
        cp_async16(xs_u + swz256(n, seg),
                   g_Xt + ((size_t)(b*NND + nt*64 + n))*NFEAT + seg*4);
    }
    #pragma unroll
    for (int i = 0; i < 8; i++) {
        int q = i*256 + tid;
        int o = q >> 4, seg = q & 15;
        const float* src = ((o < 64) ? (cv2_w + o*192) : (cv1_w + (o-64)*192)) + seg*4;
        cp_async16(cs_u0 + swz256(o, seg), src);
    }
    CP_COMMIT();
    #pragma unroll
    for (int i = 0; i < 8; i++) {
        int q = i*256 + tid;
        int o = q >> 4, seg = q & 15;
        const float* src = ((o < 64) ? (cv2_w + o*192) : (cv1_w + (o-64)*192)) + 64 + seg*4;
        cp_async16(cs_u1 + swz256(o, seg), src);
    }
    CP_COMMIT();

    uint32_t offA[2];
    #pragma unroll
    for (int t = 0; t < 2; t++) {
        int rA = wo*32 + t*16 + (mIdx & 1)*8 + (lane & 7);
        offA[t] = (uint32_t)(rA*256 + ((((mIdx >> 1) ^ (rA & 7))) << 4));
    }
    uint32_t offB[2];
    #pragma unroll
    for (int hh = 0; hh < 2; hh++) {
        int ot = hh*2 + (mIdx >> 1);
        int rB = wn*32 + ot*8 + (lane & 7);
        offB[hh] = (uint32_t)(rB*256 + ((((mIdx & 1) ^ (rB & 7))) << 4));
    }

    #pragma unroll 1
    for (int j = 0; j < JDIM; j++) {
        if (j < 2) { CP_WAIT(1); } else { CP_WAIT(0); }
        __syncthreads();
        uint32_t cu = (j == 1) ? cs_u1 : cs_u0;

        float acc[2][4][4];
        #pragma unroll
        for (int t = 0; t < 2; t++)
            #pragma unroll
            for (int ot = 0; ot < 4; ot++)
                #pragma unroll
                for (int r = 0; r < 4; r++) acc[t][ot][r] = 0.0f;

        #pragma unroll
        for (int ks = 0; ks < 8; ks++) {
            uint32_t xo = (uint32_t)(ks << 5);
            uint32_t a[2][4];
            uint32_t bq[4][2];
            #pragma unroll
            for (int t = 0; t < 2; t++)
                ldmx4(a[t], cu + (offA[t] ^ xo));
            #pragma unroll
            for (int hh = 0; hh < 2; hh++) {
                uint32_t r[4];
                ldmx4(r, xs_u + (offB[hh] ^ xo));
                bq[hh*2][0]   = r[0]; bq[hh*2][1]   = r[1];
                bq[hh*2+1][0] = r[2]; bq[hh*2+1][1] = r[3];
            }
            #pragma unroll
            for (int t = 0; t < 2; t++)
                #pragma unroll
                for (int ot = 0; ot < 4; ot++)
                    mma_tf32(acc[t][ot], a[t], bq[ot]);
        }

        #pragma unroll
        for (int t = 0; t < 2; t++)
            #pragma unroll
            for (int ot = 0; ot < 4; ot++)
                #pragma unroll
                for (int r = 0; r < 4; r++) {
                    int o = wo*32 + t*16 + g + ((r >> 1) << 3);
                    int col = (wn*32 + ot*8 + 2*tig + (r & 1))*3 + j;
                    stage[o*196 + col] = acc[t][ot][r];
                }
        __syncthreads();

        if (j == 0) {
            #pragma unroll
            for (int i = 0; i < 8; i++) {
                int q = i*256 + tid;
                int o = q >> 4, seg = q & 15;
                const float* src = ((o < 64) ? (cv2_w + o*192) : (cv1_w + (o-64)*192)) + 128 + seg*4;
                cp_async16(cs_u0 + swz256(o, seg), src);
            }
            CP_COMMIT();
        }
    }

    #pragma unroll
    for (int i = 0; i < 24; i++) {
        int q = i*256 + tid;
        int row = q / 48, c4 = q % 48;
        float4 v = *(const float4*)(stage + row*196 + c4*4);
        *(float4*)(g_P + ((size_t)(b*CH + row))*KDIM + nt*192 + c4*4) = v;
    }
}

// ---------------- K2: persistent D = W * P^T over 148 CTAs, fused W copy ----------------
__device__ __forceinline__ void k2_load_stage(char* sm, int u, int tid,
                                              const float* W, const float* P) {
    int tile = u / NCH, c = u % NCH;
    int b = tile >> 4, mt = tile & 15;
    const float* wsrc = W   + ((size_t)(b*NND + mt*MT))*KDIM + c*CHUNK;
    const float* psrc = g_P + ((size_t)(b*CH))*KDIM + c*CHUNK;
    #pragma unroll
    for (int i = 0; i < 8; i++) {
        int q = i*THR2 + tid;
        int row = q >> 4, seg = q & 15;
        cp_async16(smem_u32(sm + swz256(row, seg)), wsrc + (size_t)row*KDIM + seg*4);
    }
    #pragma unroll
    for (int i = 0; i < 8; i++) {
        int q = i*THR2 + tid;
        int row = q >> 4, seg = q & 15;
        cp_async16(smem_u32(sm + WTILEB + swz256(row, seg)), psrc + (size_t)row*KDIM + seg*4);
    }
}

__device__ __forceinline__ void k2_frags(uint32_t a[4][4], uint32_t bq[8][2],
                                         uint32_t swu, uint32_t spu, uint32_t xo,
                                         const uint32_t* offA, const uint32_t* offB) {
    #pragma unroll
    for (int mg = 0; mg < 4; mg++)
        ldmx4(a[mg], swu + (offA[mg] ^ xo));
    #pragma unroll
    for (int hh = 0; hh < 4; hh++) {
        uint32_t r[4];
        ldmx4(r, spu + (offB[hh] ^ xo));
        bq[hh*2][0] = r[0]; bq[hh*2][1] = r[1];
        bq[hh*2+1][0] = r[2]; bq[hh*2+1][1] = r[3];
    }
}

__global__ void __launch_bounds__(THR2, 1)
k2_gemm(const float* __restrict__ W, float* __restrict__ outW) {
    extern __shared__ char dyn2[];

    int tid = threadIdx.x;
    int wid = tid >> 5, lane = tid & 31;
    int p  = wid >> 1;
    int h  = wid & 1;
    int wy = p >> 1, wx = p & 1;
    int g = lane >> 2, tig = lane & 3;

    int cta = blockIdx.x;
    const int base = UNITS / NCTA2;            // 83
    const int rem  = UNITS % NCTA2;            // 4
    int start = cta*base + (cta < rem ? cta : rem);
    int end   = start + base + (cta < rem ? 1 : 0);

    uint32_t dyn_u = smem_u32(dyn2);

    int mIdx = lane >> 3;
    uint32_t offA[4];
    #pragma unroll
    for (int mg = 0; mg < 4; mg++) {
        int rA = wy*64 + mg*16 + (mIdx & 1)*8 + (lane & 7);
        offA[mg] = (uint32_t)(rA*256 + ((((mIdx >> 1) ^ (rA & 7))) << 4));
    }
    uint32_t offB[4];
    #pragma unroll
    for (int hh = 0; hh < 4; hh++) {
        int ot = hh*2 + (mIdx >> 1);
        int rB = wx*64 + ot*8 + (lane & 7);
        offB[hh] = (uint32_t)(rB*256 + ((((mIdx & 1) ^ (rB & 7))) << 4));
    }

    float acc[4][8][4];
    #pragma unroll
    for (int t = 0; t < 4; t++)
        #pragma unroll
        for (int ot = 0; ot < 8; ot++)
            #pragma unroll
            for (int r = 0; r < 4; r++) acc[t][ot][r] = 0.0f;

    #pragma unroll
    for (int s = 0; s < LOOKAHEAD; s++) {
        k2_load_stage(dyn2 + s*STAGEB, start + s, tid, W, g_P);
        CP_COMMIT();
    }

    uint32_t xo0 = (uint32_t)((h*4 + 0) << 5);
    uint32_t xo1 = (uint32_t)((h*4 + 1) << 5);
    uint32_t xo2 = (uint32_t)((h*4 + 2) << 5);
    uint32_t xo3 = (uint32_t)((h*4 + 3) << 5);

    for (int u = start; u < end; u++) {
        int it = u - start;
        int tile = u / NCH, c = u % NCH;
        int b = tile >> 4, mt = tile & 15;

        CP_WAIT(LOOKAHEAD - 1);
        __syncthreads();

        uint32_t swu = dyn_u + (uint32_t)((it % STAGES)*STAGEB);
        uint32_t spu = swu + WTILEB;
        char*    sw  = dyn2 + (it % STAGES)*STAGEB;

        uint32_t a0[4][4], b0[8][2], a1[4][4], b1[8][2];

        k2_frags(a0, b0, swu, spu, xo0, offA, offB);

        if (u + LOOKAHEAD < end)
            k2_load_stage(dyn2 + ((it + LOOKAHEAD) % STAGES)*STAGEB,
                          u + LOOKAHEAD, tid, W, g_P);
        CP_COMMIT();

        // fused W copy-out (streaming stores)
        float* wdst = outW + ((size_t)(b*NND + mt*MT))*KDIM + c*CHUNK;
        #pragma unroll
        for (int i = 0; i < 8; i++) {
            int q = i*THR2 + tid;
            int row = q >> 4, seg = q & 15;
            float4 v = *(const float4*)(sw + swz256(row, seg));
            stg16_cs(wdst + (size_t)row*KDIM + seg*4, v);
        }

        k2_frags(a1, b1, swu, spu, xo1, offA, offB);
        #pragma unroll
        for (int t = 0; t < 4; t++)
            #pragma unroll
            for (int ot = 0; ot < 8; ot++)
                mma_tf32(acc[t][ot], a0[t], b0[ot]);

        k2_frags(a0, b0, swu, spu, xo2, offA, offB);
        #pragma unroll
        for (int t = 0; t < 4; t++)
            #pragma unroll
            for (int ot = 0; ot < 8; ot++)
                mma_tf32(acc[t][ot], a1[t], b1[ot]);

        k2_frags(a1, b1, swu, spu, xo3, offA, offB);
        #pragma unroll
        for (int t = 0; t < 4; t++)
            #pragma unroll
            for (int ot = 0; ot < 8; ot++)
                mma_tf32(acc[t][ot], a0[t], b0[ot]);
        #pragma unroll
        for (int t = 0; t < 4; t++)
            #pragma unroll
            for (int ot = 0; ot < 8; ot++)
                mma_tf32(acc[t][ot], a1[t], b1[ot]);

        // flush partial D at tile boundary / range end
        if (c == NCH - 1 || u + 1 == end) {
            float* dtile = g_D + (size_t)tile*MT*CH;
            #pragma unroll
            for (int t = 0; t < 4; t++) {
                #pragma unroll
                for (int ot = 0; ot < 8; ot++) {
                    #pragma unroll
                    for (int r = 0; r < 4; r++) {
                        int m = wy*64 + t*16 + g + ((r >> 1) << 3);
                        int o = wx*64 + ot*8 + 2*tig + (r & 1);
                        atomicAdd(&dtile[m*CH + o], acc[t][ot][r]);
                        acc[t][ot][r] = 0.0f;
                    }
                }
            }
        }
    }
}

// ---------------- K2e: stats only — bias+relu on D, masked partial sums + M0 ----------------
__global__ void __launch_bounds__(256, 1)
k2e_stats(const float* __restrict__ cv1_b, const float* __restrict__ cv2_b,
          const float* __restrict__ mask) {
    extern __shared__ float sme[];
    float* sd = sme;                 // [128 m][129]
    float* sm = sme + 128*129;       // mask[128]
    int tid = threadIdx.x;
    int tile = blockIdx.x;
    int b = tile >> 4, mt = tile & 15;

    const float* dsrc = g_D + (size_t)tile*MT*CH;
    #pragma unroll
    for (int i = 0; i < 16; i++) {
        int q = i*256 + tid;
        int m = q >> 5, o4 = q & 31;
        float4 v = *(const float4*)(dsrc + m*CH + o4*4);
        float* dst = sd + m*129 + o4*4;
        dst[0] = v.x; dst[1] = v.y; dst[2] = v.z; dst[3] = v.w;
    }
    if (tid < 128) sm[tid] = mask[(size_t)b*NND + mt*128 + tid];
    __syncthreads();

    int o = tid >> 1, half = tid & 1;
    int m0 = half*64;
    float bias = (o < 64) ? cv2_b[o] : cv1_b[o - 64];
    float s1 = 0.0f, s2 = 0.0f;
    #pragma unroll
    for (int m = 0; m < 64; m++) {
        float v = fmaxf(sd[(m0 + m)*129 + o] + bias, 0.0f);
        float mk = sm[m0 + m];
        s1 += v*mk;
        s2 += v*v*mk;
    }
    s1 += __shfl_xor_sync(0xFFFFFFFFu, s1, 1);
    s2 += __shfl_xor_sync(0xFFFFFFFFu, s2, 1);
    if (half == 0) {
        g_pS1[tile*CH + o] = s1;
        g_pS2[tile*CH + o] = s2;
    }
    // M0 contribution: sum of this tile's mask (each tile covers distinct (b,m))
    if (tid < 32) {
        float ms = sm[tid] + sm[tid + 32] + sm[tid + 64] + sm[tid + 96];
        #pragma unroll
        for (int d = 16; d > 0; d >>= 1)
            ms += __shfl_xor_sync(0xFFFFFFFFu, ms, d);
        if (tid == 0) atomicAdd(&g_misc[1], ms);
    }
}

// ---------------- K2c: reduce partials, finalize scale/shift ----------------
__global__ void k2c_finstats(const float* __restrict__ gamma, const float* __restrict__ beta,
                             const float* __restrict__ Nb) {
    int o = blockIdx.x;
    int tid = threadIdx.x;               // 128 slots
    float s1 = g_pS1[tid*CH + o];
    float s2 = g_pS2[tid*CH + o];
    #pragma unroll
    for (int d = 16; d > 0; d >>= 1) {
        s1 += __shfl_xor_sync(0xFFFFFFFFu, s1, d);
        s2 += __shfl_xor_sync(0xFFFFFFFFu, s2, d);
    }
    __shared__ float r1[4], r2[4];
    if ((tid & 31) == 0) { r1[tid >> 5] = s1; r2[tid >> 5] = s2; }
    __syncthreads();
    if (tid == 0) {
        float t1 = 0.0f, t2 = 0.0f;
        #pragma unroll
        for (int i = 0; i < 4; i++) { t1 += r1[i]; t2 += r2[i]; }
        float total = 0.0f;
        #pragma unroll
        for (int i = 0; i < BS; i++) total += Nb[i];
        float M0 = g_misc[1];
        float mean = t1 / total;
        float var = (t2 - 2.0f*mean*t1 + mean*mean*M0) / total;
        float sc = gamma[o] * rsqrtf(var + 1e-5f);
        g_scale[o] = sc;
        g_shift[o] = beta[o] - mean*sc;
    }
}

// ---------------- K3: read D, bias+relu+affine+mask -> out (m-contiguous) ----------------
__global__ void __launch_bounds__(256, 1)
k3_apply(const float* __restrict__ cv1_b, const float* __restrict__ cv2_b,
         const float* __restrict__ mask, float* __restrict__ out) {
    extern __shared__ float sme[];
    float* sd = sme;                 // [128 m][129]
    float* sm = sme + 128*129;       // mask[128]
    int tid = threadIdx.x;
    int tile = blockIdx.x;
    int b = tile >> 4, mt = tile & 15;

    const float* dsrc = g_D + (size_t)tile*MT*CH;
    #pragma unroll
    for (int i = 0; i < 16; i++) {
        int q = i*256 + tid;
        int m = q >> 5, o4 = q & 31;
        float4 v = *(const float4*)(dsrc + m*CH + o4*4);
        float* dst = sd + m*129 + o4*4;
        dst[0] = v.x; dst[1] = v.y; dst[2] = v.z; dst[3] = v.w;
    }
    if (tid < 128) sm[tid] = mask[(size_t)b*NND + mt*128 + tid];
    __syncthreads();

    int o = tid >> 1, half = tid & 1;
    int m0 = half*64;
    float bias = (o < 64) ? cv2_b[o] : cv1_b[o - 64];
    float sc = g_scale[o], sh = g_shift[o];
    float* op = out + ((size_t)(b*CH + o))*NND + mt*128 + m0;
    #pragma unroll
    for (int i = 0; i < 16; i++) {
        float4 r;
        float* rp = &r.x;
        #pragma unroll
        for (int u = 0; u < 4; u++) {
            int m = i*4 + u;
            float v = fmaxf(sd[(m0 + m)*129 + o] + bias, 0.0f);
            rp[u] = (v*sc + sh)*sm[m0 + m];
        }
        stg16_cs(op + i*4, r);
    }
}

// ---------------- launch ----------------
extern "C" void kernel_launch(void* const* d_in, const int* in_sizes, int n_in,
                              void* d_out, int out_size) {
    (void)in_sizes; (void)n_in; (void)out_size;
    const float* X     = (const float*)d_in[0];
    const float* W     = (const float*)d_in[1];
    const float* Nb    = (const float*)d_in[2];
    const float* mask  = (const float*)d_in[3];
    const float* cv1_w = (const float*)d_in[4];
    const float* cv1_b = (const float*)d_in[5];
    const float* cv2_w = (const float*)d_in[6];
    const float* cv2_b = (const float*)d_in[7];
    const float* gamma = (const float*)d_in[8];
    const float* beta  = (const float*)d_in[9];
    float* out  = (float*)d_out;
    float* outW = out + ZN;

    cudaFuncSetAttribute(k1_gemm, cudaFuncAttributeMaxDynamicSharedMemorySize, DYN1);
    cudaFuncSetAttribute(k2_gemm, cudaFuncAttributeMaxDynamicSharedMemorySize, DYN2);
    cudaFuncSetAttribute(k2e_stats, cudaFuncAttributeMaxDynamicSharedMemorySize, DYNE);
    cudaFuncSetAttribute(k3_apply, cudaFuncAttributeMaxDynamicSharedMemorySize, DYNE);

    k0t_transpose<<<dim3(64, 2, 8), dim3(32, 8)>>>(X);           // launch 0
    k1_gemm<<<dim3(32, 8), 256, DYN1>>>(cv1_w, cv2_w);           // launch 1
    k_nop<<<1, 32>>>();                                          // launch 2 (slot shim)
    k2_gemm<<<NCTA2, THR2, DYN2>>>(W, outW);                     // launch 3 <- ncu slot
    k2e_stats<<<NTILE, 256, DYNE>>>(cv1_b, cv2_b, mask);         // launch 4
    k2c_finstats<<<CH, 128>>>(gamma, beta, Nb);                  // launch 5
    k3_apply<<<NTILE, 256, DYNE>>>(cv1_b, cv2_b, mask, out);     // launch 6
}